// round 3
// baseline (speedup 1.0000x reference)
#include <cuda_runtime.h>
#include <cuda_bf16.h>
#include <cstdint>

// Problem constants
#define D_MODEL 1024
#define HID     4096
#define N_KEYS  65536
#define TOP_K   6

#define NEG_INF (-3.402823466e38f)

#define SC_BLOCKS 512                       // fused scores+topk blocks
#define ROWS_PER_BLOCK (N_KEYS / SC_BLOCKS) // 128 rows per block
#define N_CAND (SC_BLOCKS * TOP_K)          // 3072 candidates

// Scratch (no device allocation allowed)
__device__ float g_q[HID];
__device__ float g_v[D_MODEL];
__device__ float g_cval[N_CAND];
__device__ int   g_cidx[N_CAND];

// ---------------------------------------------------------------------------
// warp argmax over (val, idx) — winner ends up in all lanes
// ---------------------------------------------------------------------------
__device__ __forceinline__ void warp_argmax(float& v, int& i) {
#pragma unroll
    for (int o = 16; o > 0; o >>= 1) {
        float ov = __shfl_xor_sync(0xFFFFFFFFu, v, o);
        int   oi = __shfl_xor_sync(0xFFFFFFFFu, i, o);
        if (ov > v || (ov == v && oi < i)) { v = ov; i = oi; }
    }
}

__device__ __forceinline__ float4 ldcs4(const float4* p) {
    return __ldcs(p);
}

// ---------------------------------------------------------------------------
// Kernel 1: q = Wq @ query + bq   (warp per output row), also zero g_v
// ---------------------------------------------------------------------------
__global__ void k_q(const float* __restrict__ Wq,
                    const float* __restrict__ bq,
                    const float* __restrict__ query) {
    if (blockIdx.x == 0) {
        for (int i = threadIdx.x; i < D_MODEL; i += blockDim.x) g_v[i] = 0.0f;
    }
    const int warp = (blockIdx.x * blockDim.x + threadIdx.x) >> 5;  // 0..4095
    const int lane = threadIdx.x & 31;

    const float4* w = reinterpret_cast<const float4*>(Wq + (size_t)warp * D_MODEL);
    const float4* qv = reinterpret_cast<const float4*>(query);

    float acc = 0.0f;
#pragma unroll
    for (int i = 0; i < 8; i++) {
        float4 a = ldcs4(&w[lane + 32 * i]);
        float4 b = qv[lane + 32 * i];
        acc += a.x * b.x + a.y * b.y + a.z * b.z + a.w * b.w;
    }
#pragma unroll
    for (int o = 16; o > 0; o >>= 1) acc += __shfl_xor_sync(0xFFFFFFFFu, acc, o);
    if (lane == 0) g_q[warp] = acc + bq[warp];
}

// ---------------------------------------------------------------------------
// Kernel 2: v[d] = sum_h Wk[h][d] * q[h]
// 256 blocks x 16 h-rows each; 256 threads own 4 consecutive d (float4);
// atomicAdd partials into g_v.
// ---------------------------------------------------------------------------
__global__ void k_v(const float* __restrict__ Wk) {
    const int h0 = blockIdx.x * 16;
    const int t = threadIdx.x;  // 0..255 -> float4 index

    __shared__ float sq[16];
    if (t < 16) sq[t] = g_q[h0 + t];
    __syncthreads();

    float4 acc = make_float4(0.f, 0.f, 0.f, 0.f);
#pragma unroll
    for (int j = 0; j < 16; j++) {
        float qh = sq[j];
        float4 w = ldcs4(&reinterpret_cast<const float4*>(Wk + (size_t)(h0 + j) * D_MODEL)[t]);
        acc.x += w.x * qh;
        acc.y += w.y * qh;
        acc.z += w.z * qh;
        acc.w += w.w * qh;
    }
    atomicAdd(&g_v[t * 4 + 0], acc.x);
    atomicAdd(&g_v[t * 4 + 1], acc.y);
    atomicAdd(&g_v[t * 4 + 2], acc.z);
    atomicAdd(&g_v[t * 4 + 3], acc.w);
}

// ---------------------------------------------------------------------------
// Kernel 3 (fused): scores for 128 rows per block + block top-6 epilogue.
// 512 blocks x 256 threads (8 warps); each warp streams 16 rows.
// Epilogue: threads 0..127 own one score; 6 rounds of 4-warp argmax.
// ---------------------------------------------------------------------------
__global__ void k_scores_topk(const float* __restrict__ key_mat) {
    __shared__ float4 sv[D_MODEL / 4];
    __shared__ float  sscore[ROWS_PER_BLOCK];
    __shared__ float  swv[4];
    __shared__ int    swi[4];
    __shared__ float  s_wv;
    __shared__ int    s_wi;

    const int t = threadIdx.x;
    const int warp = t >> 5;   // 0..7
    const int lane = t & 31;
    const int base = blockIdx.x * ROWS_PER_BLOCK;

    sv[t] = reinterpret_cast<const float4*>(g_v)[t];
    __syncthreads();

    // each warp: 16 rows, stride 8
#pragma unroll 1
    for (int r = warp; r < ROWS_PER_BLOCK; r += 8) {
        const float4* kr = reinterpret_cast<const float4*>(
            key_mat + (size_t)(base + r) * D_MODEL);
        float acc = 0.0f;
#pragma unroll
        for (int i = 0; i < 8; i++) {
            float4 a = ldcs4(&kr[lane + 32 * i]);
            float4 b = sv[lane + 32 * i];
            acc += a.x * b.x + a.y * b.y + a.z * b.z + a.w * b.w;
        }
#pragma unroll
        for (int o = 16; o > 0; o >>= 1) acc += __shfl_xor_sync(0xFFFFFFFFu, acc, o);
        if (lane == 0) sscore[r] = acc;
    }
    __syncthreads();

    // block top-6 over 128 scores; threads 0..127 participate
    float v = (t < ROWS_PER_BLOCK) ? sscore[t] : NEG_INF;
    int   i = (t < ROWS_PER_BLOCK) ? (base + t) : -1;

#pragma unroll
    for (int r = 0; r < TOP_K; r++) {
        if (warp < 4) {
            float bv = v; int bi = i;
            warp_argmax(bv, bi);
            if (lane == 0) { swv[warp] = bv; swi[warp] = bi; }
        }
        __syncthreads();
        if (t == 0) {
            float mv = swv[0]; int mi = swi[0];
#pragma unroll
            for (int j = 1; j < 4; j++) {
                if (swv[j] > mv || (swv[j] == mv && swi[j] < mi)) { mv = swv[j]; mi = swi[j]; }
            }
            s_wv = mv; s_wi = mi;
            g_cval[blockIdx.x * TOP_K + r] = mv;
            g_cidx[blockIdx.x * TOP_K + r] = mi;
        }
        __syncthreads();
        if (i == s_wi) v = NEG_INF;   // remove winner (indices unique)
        __syncthreads();
    }
}

// ---------------------------------------------------------------------------
// Kernel 4 (stage 2): merge 3072 candidates -> global top-6, then
// out = mean(key_mat[idx]).  1 block, 1024 threads, 3 candidates/thread
// held statically sorted in registers.
// ---------------------------------------------------------------------------
__global__ void k_topk_mean2(const float* __restrict__ key_mat,
                             float* __restrict__ out) {
    const int t = threadIdx.x;   // 0..1023
    const int lane = t & 31;
    const int warp = t >> 5;     // 0..31

    float v0 = g_cval[t],        v1 = g_cval[t + 1024], v2 = g_cval[t + 2048];
    int   i0 = g_cidx[t],        i1 = g_cidx[t + 1024], i2 = g_cidx[t + 2048];

    // sort 3 descending (static)
#define CSWP(a, b, ia, ib) { if (b > a || (b == a && ib < ia)) { float tv = a; a = b; b = tv; int ti = ia; ia = ib; ib = ti; } }
    CSWP(v0, v1, i0, i1);
    CSWP(v1, v2, i1, i2);
    CSWP(v0, v1, i0, i1);
#undef CSWP

    __shared__ float swv[32];
    __shared__ int   swi[32];
    __shared__ int   s_win[TOP_K];
    __shared__ int   s_wi;

#pragma unroll
    for (int r = 0; r < TOP_K; r++) {
        float bv = v0; int bi = i0;
        warp_argmax(bv, bi);
        if (lane == 0) { swv[warp] = bv; swi[warp] = bi; }
        __syncthreads();
        if (warp == 0) {
            float mv = swv[lane];
            int   mi = swi[lane];
            warp_argmax(mv, mi);
            if (lane == 0) { s_wi = mi; s_win[r] = mi; }
        }
        __syncthreads();
        if (i0 == s_wi) {  // pop head
            v0 = v1; i0 = i1;
            v1 = v2; i1 = i2;
            v2 = NEG_INF; i2 = -1;
        }
        __syncthreads();
    }

    // mean of the 6 selected rows (t indexes the 1024 output elements)
    float s = 0.0f;
#pragma unroll
    for (int j = 0; j < TOP_K; j++) {
        s += key_mat[(size_t)s_win[j] * D_MODEL + t];
    }
    out[t] = s * (1.0f / 6.0f);
}

// ---------------------------------------------------------------------------
extern "C" void kernel_launch(void* const* d_in, const int* in_sizes, int n_in,
                              void* d_out, int out_size) {
    const float* query   = (const float*)d_in[0];  // [1024]
    const float* key_mat = (const float*)d_in[1];  // [65536, 1024]
    const float* Wq      = (const float*)d_in[2];  // [4096, 1024]
    const float* bq      = (const float*)d_in[3];  // [4096]
    const float* Wk      = (const float*)d_in[4];  // [4096, 1024]
    // d_in[5] = bk: constant shift of all scores -> top-k indices unchanged
    float* out = (float*)d_out;                    // [1024] f32

    k_q<<<512, 256>>>(Wq, bq, query);            // 4096 warps, one per row
    k_v<<<256, 256>>>(Wk);                       // 16 h-rows per block
    k_scores_topk<<<SC_BLOCKS, 256>>>(key_mat);  // scores + block top-6 fused
    k_topk_mean2<<<1, 1024>>>(key_mat, out);     // merge + gather-mean
}

// round 4
// speedup vs baseline: 1.0266x; 1.0266x over previous
#include <cuda_runtime.h>
#include <cuda_bf16.h>
#include <cstdint>

// Problem constants
#define D_MODEL 1024
#define HID     4096
#define N_KEYS  65536
#define TOP_K   6

#define NEG_INF (-3.402823466e38f)

#define TK_BLOCKS 128                       // stage-1 blocks (~1 per SM)
#define TK_PER_BLOCK (N_KEYS / TK_BLOCKS)   // 512 scores per block
#define N_CAND (TK_BLOCKS * TOP_K)          // 768 candidates

// Scratch (no device allocation allowed)
__device__ float g_q[HID];
__device__ float g_v[D_MODEL];
__device__ float g_scores[N_KEYS];
__device__ float g_cval[N_CAND];
__device__ int   g_cidx[N_CAND];

// ---------------------------------------------------------------------------
// warp argmax over (val, idx) — winner ends up in all lanes
// ---------------------------------------------------------------------------
__device__ __forceinline__ void warp_argmax(float& v, int& i) {
#pragma unroll
    for (int o = 16; o > 0; o >>= 1) {
        float ov = __shfl_xor_sync(0xFFFFFFFFu, v, o);
        int   oi = __shfl_xor_sync(0xFFFFFFFFu, i, o);
        if (ov > v || (ov == v && oi < i)) { v = ov; i = oi; }
    }
}

__device__ __forceinline__ float4 ldcs4(const float4* p) { return __ldcs(p); }

// ---------------------------------------------------------------------------
// Kernel 1: q = Wq @ query + bq   (warp per output row), also zero g_v
// ---------------------------------------------------------------------------
__global__ void k_q(const float* __restrict__ Wq,
                    const float* __restrict__ bq,
                    const float* __restrict__ query) {
    if (blockIdx.x == 0) {
        for (int i = threadIdx.x; i < D_MODEL; i += blockDim.x) g_v[i] = 0.0f;
    }
    const int warp = (blockIdx.x * blockDim.x + threadIdx.x) >> 5;  // 0..4095
    const int lane = threadIdx.x & 31;

    const float4* w = reinterpret_cast<const float4*>(Wq + (size_t)warp * D_MODEL);
    const float4* qv = reinterpret_cast<const float4*>(query);

    float acc = 0.0f;
#pragma unroll
    for (int i = 0; i < 8; i++) {
        float4 a = ldcs4(&w[lane + 32 * i]);
        float4 b = qv[lane + 32 * i];
        acc += a.x * b.x + a.y * b.y + a.z * b.z + a.w * b.w;
    }
#pragma unroll
    for (int o = 16; o > 0; o >>= 1) acc += __shfl_xor_sync(0xFFFFFFFFu, acc, o);
    if (lane == 0) g_q[warp] = acc + bq[warp];
}

// ---------------------------------------------------------------------------
// Kernel 2: v[d] = sum_h Wk[h][d] * q[h]
// 256 blocks x 16 h-rows each; 256 threads own 4 consecutive d (float4);
// atomicAdd partials into g_v.
// ---------------------------------------------------------------------------
__global__ void k_v(const float* __restrict__ Wk) {
    const int h0 = blockIdx.x * 16;
    const int t = threadIdx.x;  // 0..255 -> float4 index

    __shared__ float sq[16];
    if (t < 16) sq[t] = g_q[h0 + t];
    __syncthreads();

    float4 acc = make_float4(0.f, 0.f, 0.f, 0.f);
#pragma unroll
    for (int j = 0; j < 16; j++) {
        float qh = sq[j];
        float4 w = ldcs4(&reinterpret_cast<const float4*>(Wk + (size_t)(h0 + j) * D_MODEL)[t]);
        acc.x += w.x * qh;
        acc.y += w.y * qh;
        acc.z += w.z * qh;
        acc.w += w.w * qh;
    }
    atomicAdd(&g_v[t * 4 + 0], acc.x);
    atomicAdd(&g_v[t * 4 + 1], acc.y);
    atomicAdd(&g_v[t * 4 + 2], acc.z);
    atomicAdd(&g_v[t * 4 + 3], acc.w);
}

// ---------------------------------------------------------------------------
// Kernel 3: scores[n] = key_mat[n] . v    (warp per row; v staged in smem)
// 8192 blocks x 256 threads — the 256 MB stream; maximal parallelism.
// ---------------------------------------------------------------------------
__global__ void k_scores(const float* __restrict__ key_mat) {
    __shared__ float4 sv[D_MODEL / 4];
    sv[threadIdx.x] = reinterpret_cast<const float4*>(g_v)[threadIdx.x];
    __syncthreads();

    const int warp = threadIdx.x >> 5;
    const int lane = threadIdx.x & 31;
    const int row = blockIdx.x * 8 + warp;

    const float4* kr = reinterpret_cast<const float4*>(key_mat + (size_t)row * D_MODEL);

    float acc = 0.0f;
#pragma unroll
    for (int i = 0; i < 8; i++) {
        float4 a = ldcs4(&kr[lane + 32 * i]);
        float4 b = sv[lane + 32 * i];
        acc += a.x * b.x + a.y * b.y + a.z * b.z + a.w * b.w;
    }
#pragma unroll
    for (int o = 16; o > 0; o >>= 1) acc += __shfl_xor_sync(0xFFFFFFFFu, acc, o);
    if (lane == 0) g_scores[row] = acc;
}

// ---------------------------------------------------------------------------
// Kernel 4 (stage 1): per-block top-6 over 512 scores -> 6 candidates/block.
// 128 blocks x 256 threads; each thread holds a register-sorted PAIR.
// ---------------------------------------------------------------------------
__global__ void k_topk_stage1() {
    const int t = threadIdx.x;            // 0..255
    const int lane = t & 31;
    const int warp = t >> 5;              // 0..7
    const int base = blockIdx.x * TK_PER_BLOCK;

    float2 x = reinterpret_cast<const float2*>(g_scores + base)[t];
    float v0 = x.x, v1 = x.y;
    int i0 = base + t * 2, i1 = base + t * 2 + 1;
    if (v1 > v0) { float tv = v0; v0 = v1; v1 = tv; int ti = i0; i0 = i1; i1 = ti; }

    __shared__ float swv[8];
    __shared__ int   swi[8];
    __shared__ int   s_wi;

#pragma unroll
    for (int r = 0; r < TOP_K; r++) {
        float bv = v0; int bi = i0;
        warp_argmax(bv, bi);
        if (lane == 0) { swv[warp] = bv; swi[warp] = bi; }
        __syncthreads();
        if (warp == 0) {
            float mv = (lane < 8) ? swv[lane] : NEG_INF;
            int   mi = (lane < 8) ? swi[lane] : -1;
            warp_argmax(mv, mi);
            if (lane == 0) {
                s_wi = mi;
                g_cval[blockIdx.x * TOP_K + r] = mv;
                g_cidx[blockIdx.x * TOP_K + r] = mi;
            }
        }
        __syncthreads();
        if (i0 == s_wi) {  // pop head (indices unique -> exactly one owner)
            v0 = v1; i0 = i1;
            v1 = NEG_INF; i1 = -1;
        }
        __syncthreads();
    }
}

// ---------------------------------------------------------------------------
// Kernel 5 (stage 2): merge 768 candidates -> global top-6, then
// out = mean(key_mat[idx]).  1 block, 1024 threads, ONE candidate/thread.
// ---------------------------------------------------------------------------
__global__ void k_topk_mean2(const float* __restrict__ key_mat,
                             float* __restrict__ out) {
    const int t = threadIdx.x;   // 0..1023
    const int lane = t & 31;
    const int warp = t >> 5;     // 0..31

    float v = (t < N_CAND) ? g_cval[t] : NEG_INF;
    int   i = (t < N_CAND) ? g_cidx[t] : -1;

    __shared__ float swv[32];
    __shared__ int   swi[32];
    __shared__ int   s_win[TOP_K];
    __shared__ int   s_wi;

#pragma unroll
    for (int r = 0; r < TOP_K; r++) {
        float bv = v; int bi = i;
        warp_argmax(bv, bi);
        if (lane == 0) { swv[warp] = bv; swi[warp] = bi; }
        __syncthreads();
        if (warp == 0) {
            float mv = swv[lane];
            int   mi = swi[lane];
            warp_argmax(mv, mi);
            if (lane == 0) { s_wi = mi; s_win[r] = mi; }
        }
        __syncthreads();
        if (i == s_wi) v = NEG_INF;  // remove winner
        __syncthreads();
    }

    // mean of the 6 selected rows (t indexes the 1024 output elements)
    float s = 0.0f;
#pragma unroll
    for (int j = 0; j < TOP_K; j++) {
        s += key_mat[(size_t)s_win[j] * D_MODEL + t];
    }
    out[t] = s * (1.0f / 6.0f);
}

// ---------------------------------------------------------------------------
extern "C" void kernel_launch(void* const* d_in, const int* in_sizes, int n_in,
                              void* d_out, int out_size) {
    const float* query   = (const float*)d_in[0];  // [1024]
    const float* key_mat = (const float*)d_in[1];  // [65536, 1024]
    const float* Wq      = (const float*)d_in[2];  // [4096, 1024]
    const float* bq      = (const float*)d_in[3];  // [4096]
    const float* Wk      = (const float*)d_in[4];  // [4096, 1024]
    // d_in[5] = bk: constant shift of all scores -> top-k indices unchanged
    float* out = (float*)d_out;                    // [1024] f32

    k_q<<<512, 256>>>(Wq, bq, query);        // 4096 warps, one per row
    k_v<<<256, 256>>>(Wk);                   // 16 h-rows per block
    k_scores<<<N_KEYS / 8, 256>>>(key_mat);  // warp per key row
    k_topk_stage1<<<TK_BLOCKS, 256>>>();     // 768 candidates
    k_topk_mean2<<<1, 1024>>>(key_mat, out); // merge + gather-mean
}

// round 5
// speedup vs baseline: 1.1000x; 1.0715x over previous
#include <cuda_runtime.h>
#include <cuda_bf16.h>
#include <cstdint>

// Problem constants
#define D_MODEL 1024
#define HID     4096
#define N_KEYS  65536
#define TOP_K   6

#define NEG_INF (-3.402823466e38f)
#define CAND_CAP 1024

// Scratch (no device allocation; zero at module load, re-zeroed by k_final)
__device__ float g_v[D_MODEL];
__device__ float g_scores[N_KEYS];
__device__ float g_cval[CAND_CAP];
__device__ int   g_cidx[CAND_CAP];
__device__ int   g_cnt;

// ---------------------------------------------------------------------------
__device__ __forceinline__ void warp_argmax(float& v, int& i) {
#pragma unroll
    for (int o = 16; o > 0; o >>= 1) {
        float ov = __shfl_xor_sync(0xFFFFFFFFu, v, o);
        int   oi = __shfl_xor_sync(0xFFFFFFFFu, i, o);
        if (ov > v || (ov == v && oi < i)) { v = ov; i = oi; }
    }
}

__device__ __forceinline__ float4 ldcs4(const float4* p) { return __ldcs(p); }

// ---------------------------------------------------------------------------
// Kernel 1 (fused q+v): block b owns h-rows [16b, 16b+16).
// Phase 1: 8 warps compute the 16 q values (2 rows/warp) from Wq/query/bq.
// Phase 2: 256 threads stream the 16 Wk rows, atomicAdd partials into g_v.
// Requires g_v == 0 on entry (invariant maintained by k_final).
// ---------------------------------------------------------------------------
__global__ void k_qv(const float* __restrict__ Wq,
                     const float* __restrict__ bq,
                     const float* __restrict__ query,
                     const float* __restrict__ Wk) {
    const int t = threadIdx.x;      // 0..255
    const int warp = t >> 5;        // 0..7
    const int lane = t & 31;
    const int h0 = blockIdx.x * 16;

    __shared__ float sq[16];
    __shared__ float4 squery[D_MODEL / 4];

    // stage query in smem (256 float4)
    squery[t] = reinterpret_cast<const float4*>(query)[t];
    __syncthreads();

    // phase 1: warp w computes q[h0+2w] and q[h0+2w+1]
#pragma unroll
    for (int rr = 0; rr < 2; rr++) {
        const int h = h0 + warp * 2 + rr;
        const float4* w4 = reinterpret_cast<const float4*>(Wq + (size_t)h * D_MODEL);
        float acc = 0.0f;
#pragma unroll
        for (int i = 0; i < 8; i++) {
            float4 a = ldcs4(&w4[lane + 32 * i]);
            float4 b = squery[lane + 32 * i];
            acc += a.x * b.x + a.y * b.y + a.z * b.z + a.w * b.w;
        }
#pragma unroll
        for (int o = 16; o > 0; o >>= 1) acc += __shfl_xor_sync(0xFFFFFFFFu, acc, o);
        if (lane == 0) sq[warp * 2 + rr] = acc + bq[h];
    }
    __syncthreads();

    // phase 2: v partial over these 16 h rows; thread owns float4 at index t
    float4 acc = make_float4(0.f, 0.f, 0.f, 0.f);
#pragma unroll
    for (int j = 0; j < 16; j++) {
        float qh = sq[j];
        float4 w = ldcs4(&reinterpret_cast<const float4*>(Wk + (size_t)(h0 + j) * D_MODEL)[t]);
        acc.x += w.x * qh;
        acc.y += w.y * qh;
        acc.z += w.z * qh;
        acc.w += w.w * qh;
    }
    atomicAdd(&g_v[t * 4 + 0], acc.x);
    atomicAdd(&g_v[t * 4 + 1], acc.y);
    atomicAdd(&g_v[t * 4 + 2], acc.z);
    atomicAdd(&g_v[t * 4 + 3], acc.w);
}

// ---------------------------------------------------------------------------
// Kernel 2: scores[n] = key_mat[n] . v  (warp per row) + threshold filter.
// scores ~ N(0, ||v||^2) exactly (keys are iid N(0,1)); T = 3*sigma passes
// ~88 of 65536 in expectation. Candidates pushed via one atomic per passing
// row. g_scores also written for the exact fallback path.
// ---------------------------------------------------------------------------
__global__ void k_scores(const float* __restrict__ key_mat) {
    __shared__ float4 sv[D_MODEL / 4];
    __shared__ float swsum[8];
    __shared__ float s_T;

    const int t = threadIdx.x;
    const int warp = t >> 5;
    const int lane = t & 31;

    float4 vv = reinterpret_cast<const float4*>(g_v)[t];
    sv[t] = vv;
    // block-local ||v||^2 -> threshold (overlaps with nothing expensive;
    // the kernel is DRAM-bound so this ALU work is free)
    float ss = vv.x * vv.x + vv.y * vv.y + vv.z * vv.z + vv.w * vv.w;
#pragma unroll
    for (int o = 16; o > 0; o >>= 1) ss += __shfl_xor_sync(0xFFFFFFFFu, ss, o);
    if (lane == 0) swsum[warp] = ss;
    __syncthreads();
    if (t == 0) {
        float tot = swsum[0] + swsum[1] + swsum[2] + swsum[3]
                  + swsum[4] + swsum[5] + swsum[6] + swsum[7];
        s_T = 3.0f * sqrtf(tot);
    }
    __syncthreads();

    const int row = blockIdx.x * 8 + warp;
    const float4* kr = reinterpret_cast<const float4*>(key_mat + (size_t)row * D_MODEL);

    float acc = 0.0f;
#pragma unroll
    for (int i = 0; i < 8; i++) {
        float4 a = ldcs4(&kr[lane + 32 * i]);
        float4 b = sv[lane + 32 * i];
        acc += a.x * b.x + a.y * b.y + a.z * b.z + a.w * b.w;
    }
#pragma unroll
    for (int o = 16; o > 0; o >>= 1) acc += __shfl_xor_sync(0xFFFFFFFFu, acc, o);
    if (lane == 0) {
        g_scores[row] = acc;
        if (acc >= s_T) {
            int slot = atomicAdd(&g_cnt, 1);
            if (slot < CAND_CAP) {
                g_cval[slot] = acc;
                g_cidx[slot] = row;
            }
        }
    }
}

// ---------------------------------------------------------------------------
// Kernel 3: select global top-6 from candidates (or exact fallback scan),
// compute out = mean(key_mat[top6]), then reset scratch for the next replay.
// ---------------------------------------------------------------------------
__global__ void k_topk_mean(const float* __restrict__ key_mat,
                            float* __restrict__ out) {
    const int t = threadIdx.x;   // 0..1023
    const int lane = t & 31;
    const int warp = t >> 5;     // 0..31

    __shared__ float swv[32];
    __shared__ int   swi[32];
    __shared__ int   s_win[TOP_K];
    __shared__ int   s_wi;

    const int cnt = g_cnt;
    const bool fast = (cnt >= TOP_K && cnt <= CAND_CAP);

    float v;
    int   i;
    // fallback local state (only touched on slow path)
    float lv[TOP_K];
    int   li[TOP_K];

    if (fast) {
        v = (t < cnt) ? g_cval[t] : NEG_INF;
        i = (t < cnt) ? g_cidx[t] : -1;
    } else {
        // exact fallback: full scan, per-thread insertion top-6 (may spill;
        // path is effectively never taken but guarantees exactness)
#pragma unroll
        for (int j = 0; j < TOP_K; j++) { lv[j] = NEG_INF; li[j] = -1; }
        const float4* s4 = reinterpret_cast<const float4*>(g_scores);
        for (int b = 0; b < 16; b++) {
            int i4 = t + 1024 * b;
            float4 x = s4[i4];
            float vals[4] = {x.x, x.y, x.z, x.w};
#pragma unroll
            for (int c = 0; c < 4; c++) {
                float xv = vals[c];
                if (xv > lv[TOP_K - 1]) {
                    int id = i4 * 4 + c;
                    int j = TOP_K - 1;
                    while (j > 0 && xv > lv[j - 1]) {
                        lv[j] = lv[j - 1]; li[j] = li[j - 1]; j--;
                    }
                    lv[j] = xv; li[j] = id;
                }
            }
        }
        v = lv[0]; i = li[0];
    }

    int p = 0;  // fallback head pointer
#pragma unroll
    for (int r = 0; r < TOP_K; r++) {
        float bv = v; int bi = i;
        warp_argmax(bv, bi);
        if (lane == 0) { swv[warp] = bv; swi[warp] = bi; }
        __syncthreads();
        if (warp == 0) {
            float mv = swv[lane];
            int   mi = swi[lane];
            warp_argmax(mv, mi);
            if (lane == 0) { s_wi = mi; s_win[r] = mi; }
        }
        __syncthreads();
        if (i == s_wi) {
            if (fast) {
                v = NEG_INF;            // candidate consumed
            } else {
                p++;                    // pop head of local sorted list
                v = (p < TOP_K) ? lv[p] : NEG_INF;
                i = (p < TOP_K) ? li[p] : -1;
            }
        }
        __syncthreads();
    }

    // mean of the 6 selected rows (t indexes the 1024 output elements)
    float s = 0.0f;
#pragma unroll
    for (int j = 0; j < TOP_K; j++) {
        s += key_mat[(size_t)s_win[j] * D_MODEL + t];
    }
    out[t] = s * (1.0f / 6.0f);

    // reset scratch so the next graph replay starts from the same state
    g_v[t] = 0.0f;
    if (t == 0) g_cnt = 0;
}

// ---------------------------------------------------------------------------
extern "C" void kernel_launch(void* const* d_in, const int* in_sizes, int n_in,
                              void* d_out, int out_size) {
    const float* query   = (const float*)d_in[0];  // [1024]
    const float* key_mat = (const float*)d_in[1];  // [65536, 1024]
    const float* Wq      = (const float*)d_in[2];  // [4096, 1024]
    const float* bq      = (const float*)d_in[3];  // [4096]
    const float* Wk      = (const float*)d_in[4];  // [4096, 1024]
    // d_in[5] = bk: constant shift of all scores -> top-k indices unchanged
    float* out = (float*)d_out;                    // [1024] f32

    k_qv<<<256, 256>>>(Wq, bq, query, Wk);     // q then v-partials, fused
    k_scores<<<N_KEYS / 8, 256>>>(key_mat);    // stream + threshold filter
    k_topk_mean<<<1, 1024>>>(key_mat, out);    // top-6 merge + gather-mean
}